// round 1
// baseline (speedup 1.0000x reference)
#include <cuda_runtime.h>

// out[i] = cos(x[i]) * cos(theta[i % 64])
// B=8, S=4096, E=1024, HD=64  ->  N = 33,554,432 elements (divisible by 4)

__global__ void __launch_bounds__(256) qab_kernel(
    const float4* __restrict__ x4,
    const float* __restrict__ theta,
    float4* __restrict__ out4,
    int nvec)
{
    __shared__ float ct[64];
    if (threadIdx.x < 64) {
        ct[threadIdx.x] = cosf(theta[threadIdx.x]);
    }
    __syncthreads();

    int i = blockIdx.x * blockDim.x + threadIdx.x;
    if (i >= nvec) return;

    float4 v = x4[i];
    // element index of v.x is 4*i; theta index = (4*i) & 63, 16B-aligned in ct[]
    int t = (i << 2) & 63;
    float4 c = *reinterpret_cast<const float4*>(&ct[t]);

    float4 r;
    r.x = cosf(v.x) * c.x;
    r.y = cosf(v.y) * c.y;
    r.z = cosf(v.z) * c.z;
    r.w = cosf(v.w) * c.w;
    out4[i] = r;
}

extern "C" void kernel_launch(void* const* d_in, const int* in_sizes, int n_in,
                              void* d_out, int out_size)
{
    const float* x     = (const float*)d_in[0];
    const float* theta = (const float*)d_in[1];
    float* out         = (float*)d_out;

    int n = out_size;            // total elements
    int nvec = n >> 2;           // float4 count (n is divisible by 4)

    int threads = 256;
    int blocks = (nvec + threads - 1) / threads;

    qab_kernel<<<blocks, threads>>>(
        (const float4*)x, theta, (float4*)out, nvec);
}

// round 2
// speedup vs baseline: 1.1825x; 1.1825x over previous
#include <cuda_runtime.h>

// out[i] = cos(x[i]) * cos(theta[i & 63])
// N = 33,554,432 fp32 elements -> 8,388,608 float4.
// Each block owns 1024 consecutive float4 (4096 floats); each thread does 4
// float4 at stride 256. Since 4*256 float4 = 1024 floats = 16*64, the theta
// index (4*i)&63 is invariant across a thread's 4 iterations.

__global__ void __launch_bounds__(256) qab_kernel(
    const float4* __restrict__ x4,
    const float* __restrict__ theta,
    float4* __restrict__ out4,
    int nvec)
{
    __shared__ float ct[64];
    if (threadIdx.x < 64) {
        ct[threadIdx.x] = cosf(theta[threadIdx.x]);  // accurate; 64 values only
    }
    __syncthreads();

    int base = blockIdx.x * 1024 + threadIdx.x;
    int t = (base << 2) & 63;                         // 16B-aligned theta slot
    float4 c = *reinterpret_cast<const float4*>(&ct[t]);

    if (base + 3 * 256 < nvec) {
        // Fast path: front-batch all 4 loads (MLP=4)
        float4 v0 = x4[base];
        float4 v1 = x4[base + 256];
        float4 v2 = x4[base + 512];
        float4 v3 = x4[base + 768];

        float4 r;
        r.x = __cosf(v0.x) * c.x; r.y = __cosf(v0.y) * c.y;
        r.z = __cosf(v0.z) * c.z; r.w = __cosf(v0.w) * c.w;
        out4[base] = r;
        r.x = __cosf(v1.x) * c.x; r.y = __cosf(v1.y) * c.y;
        r.z = __cosf(v1.z) * c.z; r.w = __cosf(v1.w) * c.w;
        out4[base + 256] = r;
        r.x = __cosf(v2.x) * c.x; r.y = __cosf(v2.y) * c.y;
        r.z = __cosf(v2.z) * c.z; r.w = __cosf(v2.w) * c.w;
        out4[base + 512] = r;
        r.x = __cosf(v3.x) * c.x; r.y = __cosf(v3.y) * c.y;
        r.z = __cosf(v3.z) * c.z; r.w = __cosf(v3.w) * c.w;
        out4[base + 768] = r;
    } else {
        // Tail path (unused for the shipped shape; kept for generality)
        #pragma unroll
        for (int k = 0; k < 4; k++) {
            int i = base + k * 256;
            if (i < nvec) {
                float4 v = x4[i];
                float4 r;
                r.x = __cosf(v.x) * c.x; r.y = __cosf(v.y) * c.y;
                r.z = __cosf(v.z) * c.z; r.w = __cosf(v.w) * c.w;
                out4[i] = r;
            }
        }
    }
}

extern "C" void kernel_launch(void* const* d_in, const int* in_sizes, int n_in,
                              void* d_out, int out_size)
{
    const float* x     = (const float*)d_in[0];
    const float* theta = (const float*)d_in[1];
    float* out         = (float*)d_out;

    int n    = out_size;     // total elements
    int nvec = n >> 2;       // float4 count

    int threads = 256;
    int vec_per_block = threads * 4;                     // 1024 float4 / block
    int blocks = (nvec + vec_per_block - 1) / vec_per_block;

    qab_kernel<<<blocks, threads>>>(
        (const float4*)x, theta, (float4*)out, nvec);
}